// round 3
// baseline (speedup 1.0000x reference)
#include <cuda_runtime.h>
#include <math.h>

#define Bsz   2
#define Lseq  2048
#define Dmod  1024
#define Hh    16
#define HD    64
#define MROWS 4096   // B*L
#define OUT_ELEMS  (MROWS * Dmod)                 // 4,194,304
#define BIAS_ELEMS (Hh * Lseq * Lseq)             // 67,108,864

// -------- scratch (no allocations allowed) --------
__device__ float g_Q[MROWS * Dmod];
__device__ float g_K[MROWS * Dmod];
__device__ float g_V[MROWS * Dmod];
__device__ float g_C[MROWS * Dmod];
__device__ float g_O[MROWS * Dmod];   // fallback target if `out` not in d_out
__device__ float g_HL[Hh * 4095];     // per-head bias by (rel+2047)

// ============================================================
// T5 relative-position bucket -> per-head bias LUT
// ============================================================
__global__ void build_headlut_kernel(const float* __restrict__ bt, float* __restrict__ hl)
{
    int idx = blockIdx.x * blockDim.x + threadIdx.x;
    if (idx >= Hh * 4095) return;
    int h = idx / 4095;
    int t = idx - h * 4095;
    int rel = t - 2047;                 // relative_position = mem - ctx = j - i
    int bucket = (rel > 0) ? 16 : 0;
    int rp = rel < 0 ? -rel : rel;
    int add;
    if (rp < 8) {
        add = rp;
    } else {
        // mirror jnp: (log(rp/8) / log(16)) * 8, truncate toward zero
        float v = (logf((float)rp * 0.125f) / 2.772588722239781f) * 8.0f;
        int lv = 8 + (int)v;
        if (rp == 16) lv = 10;
        else if (rp == 32) lv = 12;
        else if (rp == 64) lv = 14;
        add = lv > 15 ? 15 : lv;
    }
    bucket += add;
    hl[idx] = bt[bucket * Hh + h];
}

// pb[h,i,j] = hl[h*4095 + (j-i) + 2047]  — contiguous slice per row
__global__ void fill_bias_kernel(const float* __restrict__ hl, float* __restrict__ pb)
{
    int i = blockIdx.x;     // 0..2047
    int h = blockIdx.y;     // 0..15
    const float* src = hl + h * 4095 + (2047 - i);
    float4* dst = (float4*)(pb + ((size_t)(h * Lseq + i)) * Lseq);
    int j = threadIdx.x * 4;
    dst[threadIdx.x] = make_float4(src[j], src[j + 1], src[j + 2], src[j + 3]);
}

// ============================================================
// SGEMM: C[M,1024] = A[M,1024] * B[1024,1024]^T  (nn.Linear)
// ============================================================
__device__ __forceinline__ void sgemm_body(const float* __restrict__ A,
                                           const float* __restrict__ B,
                                           float* __restrict__ C)
{
    const int K = 1024, N = 1024;
    __shared__ float As[8][132];
    __shared__ float Bs[8][132];
    int tid = threadIdx.x;
    int m0 = blockIdx.y << 7;
    int n0 = blockIdx.x << 7;
    int lrow = tid >> 1;
    int lcol = (tid & 1) << 2;
    const float* Ap = A + (size_t)(m0 + lrow) * K + lcol;
    const float* Bp = B + (size_t)(n0 + lrow) * K + lcol;
    int ty = tid >> 4, tx = tid & 15;
    float acc[8][8];
#pragma unroll
    for (int r = 0; r < 8; ++r)
#pragma unroll
        for (int c = 0; c < 8; ++c) acc[r][c] = 0.f;

    for (int k0 = 0; k0 < K; k0 += 8) {
        float4 av = *(const float4*)(Ap + k0);
        float4 bv = *(const float4*)(Bp + k0);
        __syncthreads();
        As[lcol + 0][lrow] = av.x; As[lcol + 1][lrow] = av.y;
        As[lcol + 2][lrow] = av.z; As[lcol + 3][lrow] = av.w;
        Bs[lcol + 0][lrow] = bv.x; Bs[lcol + 1][lrow] = bv.y;
        Bs[lcol + 2][lrow] = bv.z; Bs[lcol + 3][lrow] = bv.w;
        __syncthreads();
#pragma unroll
        for (int kk = 0; kk < 8; ++kk) {
            float4 a0 = *(const float4*)&As[kk][ty * 8];
            float4 a1 = *(const float4*)&As[kk][ty * 8 + 4];
            float4 b0 = *(const float4*)&Bs[kk][tx * 8];
            float4 b1 = *(const float4*)&Bs[kk][tx * 8 + 4];
            float ar[8] = {a0.x, a0.y, a0.z, a0.w, a1.x, a1.y, a1.z, a1.w};
            float br[8] = {b0.x, b0.y, b0.z, b0.w, b1.x, b1.y, b1.z, b1.w};
#pragma unroll
            for (int r = 0; r < 8; ++r)
#pragma unroll
                for (int c = 0; c < 8; ++c) acc[r][c] = fmaf(ar[r], br[c], acc[r][c]);
        }
    }
#pragma unroll
    for (int r = 0; r < 8; ++r) {
        float* Cp = C + (size_t)(m0 + ty * 8 + r) * N + n0 + tx * 8;
        *(float4*)Cp       = make_float4(acc[r][0], acc[r][1], acc[r][2], acc[r][3]);
        *(float4*)(Cp + 4) = make_float4(acc[r][4], acc[r][5], acc[r][6], acc[r][7]);
    }
}

__global__ void __launch_bounds__(256) sgemm_qkv_kernel(
    const float* __restrict__ A,
    const float* __restrict__ W0, const float* __restrict__ W1, const float* __restrict__ W2,
    float* __restrict__ C0, float* __restrict__ C1, float* __restrict__ C2)
{
    const float* B = (blockIdx.z == 0) ? W0 : (blockIdx.z == 1 ? W1 : W2);
    float* C = (blockIdx.z == 0) ? C0 : (blockIdx.z == 1 ? C1 : C2);
    sgemm_body(A, B, C);
}

__global__ void __launch_bounds__(256) sgemm_out_kernel(
    const float* __restrict__ A, const float* __restrict__ B, float* __restrict__ C)
{
    sgemm_body(A, B, C);
}

// ============================================================
// Flash attention: per (b, h, 128-query tile), stream 128-key tiles.
// S phase: 16x16 threads, 8x8 micro (128x128 scores).
// PV phase: 32x8 threads, 4x8 micro (128x64 output).
// Per-row softmax state in shared memory.
// ============================================================
#define QT 128
#define KT 128
#define PADI 132
#define PADC 68
#define ATTN_SMEM ((64 * PADI + KT * PADI + KT * PADC + 256 + 3 * 128) * 4)

__global__ void __launch_bounds__(256, 1) attn_kernel(
    const float* __restrict__ Q, const float* __restrict__ Kg,
    const float* __restrict__ Vg, const float* __restrict__ hl,
    float* __restrict__ ctx)
{
    extern __shared__ float sm[];
    float* Qst = sm;                   // [64][PADI]  (Q transposed: [d][i])
    float* KP  = Qst + 64 * PADI;      // K as [d][j] (64 rows), then P as [j][i] (128 rows)
    float* Vs  = KP + KT * PADI;       // [j][c]  (c < 64)
    float* win = Vs + KT * PADC;       // 255 bias values for this (q-tile, k-tile)
    float* sm_m = win + 256;           // [128] row max
    float* sm_l = sm_m + 128;          // [128] row sum
    float* sm_a = sm_l + 128;          // [128] row alpha (this tile)

    int tid = threadIdx.x;
    int q0 = blockIdx.x * QT;
    int h  = blockIdx.y;
    int b  = blockIdx.z;
    const float* Qb = Q  + (size_t)b * Lseq * Dmod + h * HD;
    const float* Kb = Kg + (size_t)b * Lseq * Dmod + h * HD;
    const float* Vb = Vg + (size_t)b * Lseq * Dmod + h * HD;
    const float* hlh = hl + h * 4095;

    // load Q tile, transposed to [d][i]
#pragma unroll
    for (int r = 0; r < 32; ++r) {
        int idx = r * 256 + tid;
        int i = idx >> 6, d = idx & 63;
        Qst[d * PADI + i] = Qb[(size_t)(q0 + i) * Dmod + d];
    }
    if (tid < 128) { sm_m[tid] = -1e30f; sm_l[tid] = 0.f; }

    int ty = tid >> 4, tx = tid & 15;       // S phase
    int ty2 = tid >> 3, tx2 = tid & 7;      // PV phase
    float O[4][8];
#pragma unroll
    for (int r = 0; r < 4; ++r)
#pragma unroll
        for (int c = 0; c < 8; ++c) O[r][c] = 0.f;

    for (int k0 = 0; k0 < Lseq; k0 += KT) {
        __syncthreads();   // prev PV done (and Q load / state init on first iter)
#pragma unroll
        for (int r = 0; r < 32; ++r) {
            int idx = r * 256 + tid;
            int j = idx >> 6, d = idx & 63;
            KP[d * PADI + j] = Kb[(size_t)(k0 + j) * Dmod + d];
            Vs[j * PADC + d] = Vb[(size_t)(k0 + j) * Dmod + d];
        }
        if (tid < 255) win[tid] = hlh[(k0 - q0 - 127 + 2047) + tid];
        __syncthreads();

        // S = Q * K^T  (128x128)
        float S[8][8];
#pragma unroll
        for (int r = 0; r < 8; ++r)
#pragma unroll
            for (int c = 0; c < 8; ++c) S[r][c] = 0.f;
#pragma unroll 8
        for (int d = 0; d < HD; ++d) {
            float4 a0 = *(const float4*)&Qst[d * PADI + ty * 8];
            float4 a1 = *(const float4*)&Qst[d * PADI + ty * 8 + 4];
            float4 b0 = *(const float4*)&KP[d * PADI + tx * 8];
            float4 b1 = *(const float4*)&KP[d * PADI + tx * 8 + 4];
            float ar[8] = {a0.x, a0.y, a0.z, a0.w, a1.x, a1.y, a1.z, a1.w};
            float br[8] = {b0.x, b0.y, b0.z, b0.w, b1.x, b1.y, b1.z, b1.w};
#pragma unroll
            for (int r = 0; r < 8; ++r)
#pragma unroll
                for (int c = 0; c < 8; ++c) S[r][c] = fmaf(ar[r], br[c], S[r][c]);
        }

        // bias: rel = (k0+j) - (q0+i); win index = (j-i)+127
        int dji = tx * 8 - ty * 8 + 127;
#pragma unroll
        for (int r = 0; r < 8; ++r)
#pragma unroll
            for (int c = 0; c < 8; ++c) S[r][c] += win[dji + c - r];

        // online softmax: rows i = ty*8 + r, 16 lanes (same ty) per row
#pragma unroll
        for (int r = 0; r < 8; ++r) {
            int row = ty * 8 + r;
            float tm = S[r][0];
#pragma unroll
            for (int c = 1; c < 8; ++c) tm = fmaxf(tm, S[r][c]);
            tm = fmaxf(tm, __shfl_xor_sync(0xffffffffu, tm, 1));
            tm = fmaxf(tm, __shfl_xor_sync(0xffffffffu, tm, 2));
            tm = fmaxf(tm, __shfl_xor_sync(0xffffffffu, tm, 4));
            tm = fmaxf(tm, __shfl_xor_sync(0xffffffffu, tm, 8));
            float mo = sm_m[row];
            float mn = fmaxf(mo, tm);
            float rs = 0.f;
#pragma unroll
            for (int c = 0; c < 8; ++c) { S[r][c] = expf(S[r][c] - mn); rs += S[r][c]; }
            rs += __shfl_xor_sync(0xffffffffu, rs, 1);
            rs += __shfl_xor_sync(0xffffffffu, rs, 2);
            rs += __shfl_xor_sync(0xffffffffu, rs, 4);
            rs += __shfl_xor_sync(0xffffffffu, rs, 8);
            if (tx == 0) {
                float alpha = expf(mo - mn);
                sm_a[row] = alpha;
                sm_m[row] = mn;
                sm_l[row] = sm_l[row] * alpha + rs;
            }
        }

        __syncthreads();   // K reads done; sm_a/sm_m/sm_l published
        // store P transposed: KP[j][i]
#pragma unroll
        for (int c = 0; c < 8; ++c) {
            int j = tx * 8 + c;
            *(float4*)&KP[j * PADI + ty * 8]     = make_float4(S[0][c], S[1][c], S[2][c], S[3][c]);
            *(float4*)&KP[j * PADI + ty * 8 + 4] = make_float4(S[4][c], S[5][c], S[6][c], S[7][c]);
        }
        __syncthreads();

        // O scale by alpha, then O += P * V   (rows i = ty2*4 + r, cols c = tx2*8..)
#pragma unroll
        for (int r = 0; r < 4; ++r) {
            float alpha = sm_a[ty2 * 4 + r];
#pragma unroll
            for (int c = 0; c < 8; ++c) O[r][c] *= alpha;
        }
#pragma unroll 8
        for (int j = 0; j < KT; ++j) {
            float4 pa = *(const float4*)&KP[j * PADI + ty2 * 4];
            float4 b0 = *(const float4*)&Vs[j * PADC + tx2 * 8];
            float4 b1 = *(const float4*)&Vs[j * PADC + tx2 * 8 + 4];
            float ar[4] = {pa.x, pa.y, pa.z, pa.w};
            float br[8] = {b0.x, b0.y, b0.z, b0.w, b1.x, b1.y, b1.z, b1.w};
#pragma unroll
            for (int r = 0; r < 4; ++r)
#pragma unroll
                for (int c = 0; c < 8; ++c) O[r][c] = fmaf(ar[r], br[c], O[r][c]);
        }
    }

    // epilogue: normalize and write ctx[(b*L + i), h*64 + c]   (c < 64)
#pragma unroll
    for (int r = 0; r < 4; ++r) {
        float inv = 1.f / sm_l[ty2 * 4 + r];
        float* Cp = ctx + (size_t)(b * Lseq + q0 + ty2 * 4 + r) * Dmod + h * HD + tx2 * 8;
        *(float4*)Cp       = make_float4(O[r][0] * inv, O[r][1] * inv, O[r][2] * inv, O[r][3] * inv);
        *(float4*)(Cp + 4) = make_float4(O[r][4] * inv, O[r][5] * inv, O[r][6] * inv, O[r][7] * inv);
    }
}

// ============================================================
extern "C" void kernel_launch(void* const* d_in, const int* in_sizes, int n_in,
                              void* d_out, int out_size)
{
    const float* X  = (const float*)d_in[0];
    const float* Wq = (const float*)d_in[1];
    const float* Wk = (const float*)d_in[2];
    const float* Wv = (const float*)d_in[3];
    const float* Wo = (const float*)d_in[4];
    const float* bt = (const float*)d_in[5];
    float* out = (float*)d_out;

    float *Qb, *Kb, *Vb, *Cb, *Ob, *HL;
    cudaGetSymbolAddress((void**)&Qb, g_Q);
    cudaGetSymbolAddress((void**)&Kb, g_K);
    cudaGetSymbolAddress((void**)&Vb, g_V);
    cudaGetSymbolAddress((void**)&Cb, g_C);
    cudaGetSymbolAddress((void**)&Ob, g_O);
    cudaGetSymbolAddress((void**)&HL, g_HL);

    // ---- derive output layout from out_size ----
    float* outp = Ob;
    float* pbp  = nullptr;
    long long osz = (long long)out_size;
    if (osz >= (long long)OUT_ELEMS + (long long)BIAS_ELEMS) {
        outp = out;
        pbp  = out + (osz - (long long)BIAS_ELEMS);
    } else if (osz == (long long)BIAS_ELEMS) {
        pbp  = out;
    } else if (osz >= (long long)OUT_ELEMS) {
        outp = out;
    }

    cudaFuncSetAttribute(attn_kernel, cudaFuncAttributeMaxDynamicSharedMemorySize, ATTN_SMEM);

    build_headlut_kernel<<<(Hh * 4095 + 255) / 256, 256>>>(bt, HL);
    if (pbp) fill_bias_kernel<<<dim3(Lseq, Hh), 512>>>(HL, pbp);
    sgemm_qkv_kernel<<<dim3(8, 32, 3), 256>>>(X, Wq, Wk, Wv, Qb, Kb, Vb);
    attn_kernel<<<dim3(Lseq / QT, Hh, Bsz), 256, ATTN_SMEM>>>(Qb, Kb, Vb, HL, Cb);
    sgemm_out_kernel<<<dim3(8, 32), 256>>>(Cb, Wo, outp);
}

// round 5
// speedup vs baseline: 1.8364x; 1.8364x over previous
#include <cuda_runtime.h>
#include <cuda_bf16.h>
#include <math.h>
#include <stdint.h>

#define Bsz   2
#define Lseq  2048
#define Dmod  1024
#define Hh    16
#define HD    64
#define MROWS 4096
#define BH    32
#define OUT_ELEMS  (MROWS * Dmod)
#define BIAS_ELEMS (Hh * Lseq * Lseq)
#define SEQ2  4194304ULL

typedef __nv_bfloat16 bf16;

// ---------------- scratch ----------------
__device__ bf16 g_Xhi[MROWS * Dmod], g_Xlo[MROWS * Dmod];
__device__ bf16 g_Whi[4 * Dmod * Dmod], g_Wlo[4 * Dmod * Dmod];
__device__ bf16 g_Qhi[BH * Lseq * HD], g_Qlo[BH * Lseq * HD];
__device__ bf16 g_Khi[BH * Lseq * HD], g_Klo[BH * Lseq * HD];
__device__ bf16 g_Vthi[BH * HD * Lseq], g_Vtlo[BH * HD * Lseq];
__device__ bf16 g_Chi[MROWS * Dmod], g_Clo[MROWS * Dmod];
__device__ float g_F[MROWS * Dmod];                 // fp32 GEMM scratch (16 MB)
__device__ float g_S[BH * SEQ2];                    // 512 MB scores
__device__ bf16  g_Phi[BH * SEQ2], g_Plo[BH * SEQ2];
__device__ float g_HL[Hh * 4095];
__device__ float g_O[OUT_ELEMS];

// ============================================================
// warp-mma helpers (base PTX: sm_80+, assembles at compute_103)
// ============================================================
__device__ __forceinline__ uint32_t smem_u32(const void* p) {
    uint32_t a;
    asm("{ .reg .u64 t; cvta.to.shared.u64 t, %1; cvt.u32.u64 %0, t; }" : "=r"(a) : "l"(p));
    return a;
}
__device__ __forceinline__ void ldsm4(uint32_t* r, uint32_t addr) {
    asm volatile("ldmatrix.sync.aligned.m8n8.x4.shared.b16 {%0,%1,%2,%3}, [%4];"
        : "=r"(r[0]), "=r"(r[1]), "=r"(r[2]), "=r"(r[3]) : "r"(addr));
}
__device__ __forceinline__ void mma_bf16(float* c, const uint32_t* a, const uint32_t* b) {
    asm volatile(
        "mma.sync.aligned.m16n8k16.row.col.f32.bf16.bf16.f32 "
        "{%0,%1,%2,%3}, {%4,%5,%6,%7}, {%8,%9}, {%0,%1,%2,%3};"
        : "+f"(c[0]), "+f"(c[1]), "+f"(c[2]), "+f"(c[3])
        : "r"(a[0]), "r"(a[1]), "r"(a[2]), "r"(a[3]), "r"(b[0]), "r"(b[1]));
}

// ============================================================
// T5 bias LUT + bias fill (verified R3)
// ============================================================
__global__ void build_headlut_kernel(const float* __restrict__ bt, float* __restrict__ hl)
{
    int idx = blockIdx.x * blockDim.x + threadIdx.x;
    if (idx >= Hh * 4095) return;
    int h = idx / 4095;
    int t = idx - h * 4095;
    int rel = t - 2047;
    int bucket = (rel > 0) ? 16 : 0;
    int rp = rel < 0 ? -rel : rel;
    int add;
    if (rp < 8) {
        add = rp;
    } else {
        float v = (logf((float)rp * 0.125f) / 2.772588722239781f) * 8.0f;
        int lv = 8 + (int)v;
        if (rp == 16) lv = 10;
        else if (rp == 32) lv = 12;
        else if (rp == 64) lv = 14;
        add = lv > 15 ? 15 : lv;
    }
    bucket += add;
    hl[idx] = bt[bucket * Hh + h];
}

__global__ void fill_bias_kernel(const float* __restrict__ hl, float* __restrict__ pb)
{
    int i = blockIdx.x;
    int h = blockIdx.y;
    const float* src = hl + h * 4095 + (2047 - i);
    float4* dst = (float4*)(pb + ((size_t)(h * Lseq + i)) * Lseq);
    int j = threadIdx.x * 4;
    dst[threadIdx.x] = make_float4(src[j], src[j + 1], src[j + 2], src[j + 3]);
}

// ============================================================
// elementwise split / pack kernels
// ============================================================
__device__ __forceinline__ void split1(float x, bf16& h, bf16& l) {
    h = __float2bfloat16(x);
    l = __float2bfloat16(x - __bfloat162float(h));
}

__global__ void split_kernel(const float* __restrict__ s, bf16* __restrict__ hi,
                             bf16* __restrict__ lo, int n)
{
    int i = blockIdx.x * 256 + threadIdx.x;
    if (i >= n) return;
    split1(s[i], hi[i], lo[i]);
}

// F [b*2048+l][h*64+d] -> out [(b*16+h)][l][d]
__global__ void qk_pack_kernel(const float* __restrict__ F, bf16* __restrict__ hi,
                               bf16* __restrict__ lo)
{
    int i = blockIdx.x * 256 + threadIdx.x;   // 4M
    int row = i >> 10, col = i & 1023;
    int b = row >> 11, l = row & 2047, h = col >> 6, d = col & 63;
    size_t o = (((size_t)(b * Hh + h)) * Lseq + l) * HD + d;
    split1(F[i], hi[o], lo[o]);
}

// F [b*2048+l][h*64+d] -> Vt [(b*16+h)][d][l]   (32x32 smem transpose)
__global__ void v_packT_kernel(const float* __restrict__ F, bf16* __restrict__ hi,
                               bf16* __restrict__ lo)
{
    __shared__ float t[32][33];
    int bh = blockIdx.z, b = bh >> 4, h = bh & 15;
    int l0 = blockIdx.x * 32, d0 = blockIdx.y * 32;
    int tx = threadIdx.x, ty = threadIdx.y;   // block (32,8)
#pragma unroll
    for (int r = 0; r < 4; ++r) {
        int l = l0 + ty + r * 8;
        t[ty + r * 8][tx] = F[((size_t)(b * Lseq + l)) * Dmod + h * HD + d0 + tx];
    }
    __syncthreads();
#pragma unroll
    for (int r = 0; r < 4; ++r) {
        int d = d0 + ty + r * 8;
        int l = l0 + tx;
        size_t o = ((size_t)bh * HD + d) * Lseq + l;
        split1(t[tx][ty + r * 8], hi[o], lo[o]);
    }
}

// F [bh][l][64] -> ctx [(b*2048+l)][h*64+d]
__global__ void ctx_pack_kernel(const float* __restrict__ F, bf16* __restrict__ hi,
                                bf16* __restrict__ lo)
{
    int i = blockIdx.x * 256 + threadIdx.x;   // 4M
    int bh = i >> 17, rest = i & 131071;
    int l = rest >> 6, d = rest & 63;
    int b = bh >> 4, h = bh & 15;
    size_t o = ((size_t)(b * Lseq + l)) * Dmod + h * HD + d;
    split1(F[i], hi[o], lo[o]);
}

// ============================================================
// split-bf16 HMMA GEMM: D[M,N] fp32 = A[M,K] * B[N,K]^T
// block tile 128 x NTILE, 8 warps, K-chunk 32.
// 3-term: Ahi*Bhi + Ahi*Blo + Alo*Bhi
// ============================================================
#define PITCH 40

template<int NTILE>
__global__ void __launch_bounds__(256, 1) hgemm_kernel(
    const bf16* __restrict__ Ahi, const bf16* __restrict__ Alo,
    const bf16* __restrict__ Bhi, const bf16* __restrict__ Blo,
    int lda, int ldb, int kTot,
    long long aBatch, long long bBatch,
    float* __restrict__ outF, long long outLd, long long outBatch)
{
    constexpr int WGN = (NTILE == 128) ? 4 : 2;   // warps along n
    constexpr int WM  = (NTILE == 128) ? 64 : 32; // warp m extent
    constexpr int MF  = WM / 16;                  // m16 frags per warp
    constexpr int BV  = NTILE * 32 / (256 * 8);   // uint4 loads per thread per B half

    __shared__ __align__(16) bf16 sAh[128 * PITCH], sAl[128 * PITCH];
    __shared__ __align__(16) bf16 sBh[NTILE * PITCH], sBl[NTILE * PITCH];

    int tid = threadIdx.x, lane = tid & 31, wid = tid >> 5;
    int wm = wid / WGN, wn = wid % WGN;
    int z = blockIdx.z, m0 = blockIdx.y << 7, n0 = blockIdx.x * NTILE;

    const bf16* Abh = Ahi + (size_t)z * aBatch + (size_t)m0 * lda;
    const bf16* Abl = Alo + (size_t)z * aBatch + (size_t)m0 * lda;
    const bf16* Bbh = Bhi + (size_t)z * bBatch + (size_t)n0 * ldb;
    const bf16* Bbl = Blo + (size_t)z * bBatch + (size_t)n0 * ldb;

    uint32_t sAh32 = smem_u32(sAh), sAl32 = smem_u32(sAl);
    uint32_t sBh32 = smem_u32(sBh), sBl32 = smem_u32(sBl);

    float c[MF][4][4];
#pragma unroll
    for (int im = 0; im < MF; ++im)
#pragma unroll
        for (int nf = 0; nf < 4; ++nf)
#pragma unroll
            for (int e = 0; e < 4; ++e) c[im][nf][e] = 0.f;

    // ldmatrix lane-offsets (element units within tile arrays)
    uint32_t aOffBase[MF];
#pragma unroll
    for (int im = 0; im < MF; ++im)
        aOffBase[im] = (uint32_t)((wm * WM + im * 16 + (lane & 15)) * PITCH + ((lane >> 4) << 3));
    uint32_t bOffBase[2];
#pragma unroll
    for (int p = 0; p < 2; ++p) {
        int row = wn * 32 + p * 16 + ((lane & 16) >> 1) + (lane & 7);
        int kq = (lane & 8) ? 8 : 0;
        bOffBase[p] = (uint32_t)(row * PITCH + kq);
    }

    int nChunks = kTot >> 5;
    for (int kc = 0; kc < nChunks; ++kc) {
        int k0 = kc << 5;
        uint4 rA[2][2], rB[2][BV];
#pragma unroll
        for (int v = 0; v < 2; ++v) {
            int idx = v * 256 + tid;
            int row = idx >> 2, seg = idx & 3;
            rA[0][v] = *(const uint4*)(Abh + (size_t)row * lda + k0 + seg * 8);
            rA[1][v] = *(const uint4*)(Abl + (size_t)row * lda + k0 + seg * 8);
        }
#pragma unroll
        for (int v = 0; v < BV; ++v) {
            int idx = v * 256 + tid;
            int row = idx >> 2, seg = idx & 3;
            rB[0][v] = *(const uint4*)(Bbh + (size_t)row * ldb + k0 + seg * 8);
            rB[1][v] = *(const uint4*)(Bbl + (size_t)row * ldb + k0 + seg * 8);
        }
        if (kc > 0) __syncthreads();
#pragma unroll
        for (int v = 0; v < 2; ++v) {
            int idx = v * 256 + tid;
            int row = idx >> 2, seg = idx & 3;
            *(uint4*)(sAh + row * PITCH + seg * 8) = rA[0][v];
            *(uint4*)(sAl + row * PITCH + seg * 8) = rA[1][v];
        }
#pragma unroll
        for (int v = 0; v < BV; ++v) {
            int idx = v * 256 + tid;
            int row = idx >> 2, seg = idx & 3;
            *(uint4*)(sBh + row * PITCH + seg * 8) = rB[0][v];
            *(uint4*)(sBl + row * PITCH + seg * 8) = rB[1][v];
        }
        __syncthreads();

#pragma unroll
        for (int ks = 0; ks < 32; ks += 16) {
            uint32_t aH[MF][4], aL[MF][4], bHf[2][4], bLf[2][4];
#pragma unroll
            for (int im = 0; im < MF; ++im) {
                uint32_t off = (aOffBase[im] + ks) * 2;
                ldsm4(aH[im], sAh32 + off);
                ldsm4(aL[im], sAl32 + off);
            }
#pragma unroll
            for (int p = 0; p < 2; ++p) {
                uint32_t off = (bOffBase[p] + ks) * 2;
                ldsm4(bHf[p], sBh32 + off);
                ldsm4(bLf[p], sBl32 + off);
            }
#pragma unroll
            for (int im = 0; im < MF; ++im)
#pragma unroll
                for (int nf = 0; nf < 4; ++nf)
                    mma_bf16(c[im][nf], aH[im], &bHf[nf >> 1][(nf & 1) * 2]);
#pragma unroll
            for (int im = 0; im < MF; ++im)
#pragma unroll
                for (int nf = 0; nf < 4; ++nf)
                    mma_bf16(c[im][nf], aH[im], &bLf[nf >> 1][(nf & 1) * 2]);
#pragma unroll
            for (int im = 0; im < MF; ++im)
#pragma unroll
                for (int nf = 0; nf < 4; ++nf)
                    mma_bf16(c[im][nf], aL[im], &bHf[nf >> 1][(nf & 1) * 2]);
        }
    }

    // epilogue: c0,c1 at (row, col), c2,c3 at (row+8, col)
    float* outZ = outF + (size_t)z * outBatch;
#pragma unroll
    for (int im = 0; im < MF; ++im) {
#pragma unroll
        for (int nf = 0; nf < 4; ++nf) {
            int row = m0 + wm * WM + im * 16 + (lane >> 2);
            int col = n0 + wn * 32 + nf * 8 + 2 * (lane & 3);
            float* p0 = outZ + (size_t)row * outLd + col;
            float* p1 = outZ + (size_t)(row + 8) * outLd + col;
            *(float2*)p0 = make_float2(c[im][nf][0], c[im][nf][1]);
            *(float2*)p1 = make_float2(c[im][nf][2], c[im][nf][3]);
        }
    }
}

// ============================================================
// softmax over full row (2048) with bias; writes P hi/lo (verified logic R4)
// ============================================================
__global__ void __launch_bounds__(256) softmax_kernel(
    const float* __restrict__ S, const float* __restrict__ hl,
    bf16* __restrict__ Phi, bf16* __restrict__ Plo)
{
    __shared__ float red[8];
    __shared__ float bcast;
    int row = blockIdx.x;
    int bh = row >> 11, i = row & 2047, h = bh & 15;
    const float* sr = S + (size_t)row * Lseq;
    const float* br = hl + h * 4095 + (2047 - i);
    int tid = threadIdx.x;
    int wid = tid >> 5, lane = tid & 31;
    int j0 = tid * 8;

    float v[8];
    float4 a = *(const float4*)(sr + j0);
    float4 b2 = *(const float4*)(sr + j0 + 4);
    v[0] = a.x + br[j0];      v[1] = a.y + br[j0 + 1];
    v[2] = a.z + br[j0 + 2];  v[3] = a.w + br[j0 + 3];
    v[4] = b2.x + br[j0 + 4]; v[5] = b2.y + br[j0 + 5];
    v[6] = b2.z + br[j0 + 6]; v[7] = b2.w + br[j0 + 7];

    float mx = v[0];
#pragma unroll
    for (int c = 1; c < 8; ++c) mx = fmaxf(mx, v[c]);
#pragma unroll
    for (int o = 16; o > 0; o >>= 1) mx = fmaxf(mx, __shfl_xor_sync(0xffffffffu, mx, o));
    if (lane == 0) red[wid] = mx;
    __syncthreads();
    if (tid == 0) {
        float m = red[0];
#pragma unroll
        for (int w = 1; w < 8; ++w) m = fmaxf(m, red[w]);
        bcast = m;
    }
    __syncthreads();
    mx = bcast;

    float s = 0.f;
#pragma unroll
    for (int c = 0; c < 8; ++c) { v[c] = expf(v[c] - mx); s += v[c]; }
#pragma unroll
    for (int o = 16; o > 0; o >>= 1) s += __shfl_xor_sync(0xffffffffu, s, o);
    if (lane == 0) red[wid] = s;
    __syncthreads();
    if (tid == 0) {
        float t = 0.f;
#pragma unroll
        for (int w = 0; w < 8; ++w) t += red[w];
        bcast = 1.f / t;
    }
    __syncthreads();
    float inv = bcast;

    bf16 hb[8], lb[8];
#pragma unroll
    for (int c = 0; c < 8; ++c) split1(v[c] * inv, hb[c], lb[c]);
    *(uint4*)(Phi + (size_t)row * Lseq + j0) = *(uint4*)hb;
    *(uint4*)(Plo + (size_t)row * Lseq + j0) = *(uint4*)lb;
}

// ============================================================
extern "C" void kernel_launch(void* const* d_in, const int* in_sizes, int n_in,
                              void* d_out, int out_size)
{
    const float* X  = (const float*)d_in[0];
    const float* Wq = (const float*)d_in[1];
    const float* Wk = (const float*)d_in[2];
    const float* Wv = (const float*)d_in[3];
    const float* Wo = (const float*)d_in[4];
    const float* bt = (const float*)d_in[5];
    float* out = (float*)d_out;

    void *pXhi, *pXlo, *pWhi, *pWlo, *pQhi, *pQlo, *pKhi, *pKlo,
         *pVthi, *pVtlo, *pChi, *pClo, *pF, *pS, *pPhi, *pPlo, *pHL, *pO;
    cudaGetSymbolAddress(&pXhi, g_Xhi);   cudaGetSymbolAddress(&pXlo, g_Xlo);
    cudaGetSymbolAddress(&pWhi, g_Whi);   cudaGetSymbolAddress(&pWlo, g_Wlo);
    cudaGetSymbolAddress(&pQhi, g_Qhi);   cudaGetSymbolAddress(&pQlo, g_Qlo);
    cudaGetSymbolAddress(&pKhi, g_Khi);   cudaGetSymbolAddress(&pKlo, g_Klo);
    cudaGetSymbolAddress(&pVthi, g_Vthi); cudaGetSymbolAddress(&pVtlo, g_Vtlo);
    cudaGetSymbolAddress(&pChi, g_Chi);   cudaGetSymbolAddress(&pClo, g_Clo);
    cudaGetSymbolAddress(&pF, g_F);       cudaGetSymbolAddress(&pS, g_S);
    cudaGetSymbolAddress(&pPhi, g_Phi);   cudaGetSymbolAddress(&pPlo, g_Plo);
    cudaGetSymbolAddress(&pHL, g_HL);     cudaGetSymbolAddress(&pO, g_O);

    bf16 *Xhi = (bf16*)pXhi, *Xlo = (bf16*)pXlo;
    bf16 *Whi = (bf16*)pWhi, *Wlo = (bf16*)pWlo;
    bf16 *Qhi = (bf16*)pQhi, *Qlo = (bf16*)pQlo;
    bf16 *Khi = (bf16*)pKhi, *Klo = (bf16*)pKlo;
    bf16 *Vthi = (bf16*)pVthi, *Vtlo = (bf16*)pVtlo;
    bf16 *Chi = (bf16*)pChi, *Clo = (bf16*)pClo;
    bf16 *Phi = (bf16*)pPhi, *Plo = (bf16*)pPlo;
    float *Fb = (float*)pF, *Sb = (float*)pS, *HL = (float*)pHL, *Ob = (float*)pO;

    float* outp = Ob;
    float* pbp  = nullptr;
    long long osz = (long long)out_size;
    if (osz >= (long long)OUT_ELEMS + (long long)BIAS_ELEMS) {
        outp = out; pbp = out + (osz - (long long)BIAS_ELEMS);
    } else if (osz == (long long)BIAS_ELEMS) {
        pbp = out;
    } else if (osz >= (long long)OUT_ELEMS) {
        outp = out;
    }

    const int WSZ = Dmod * Dmod;

    build_headlut_kernel<<<(Hh * 4095 + 255) / 256, 256>>>(bt, HL);
    if (pbp) fill_bias_kernel<<<dim3(Lseq, Hh), 512>>>(HL, pbp);

    split_kernel<<<(OUT_ELEMS + 255) / 256, 256>>>(X, Xhi, Xlo, OUT_ELEMS);
    split_kernel<<<(WSZ + 255) / 256, 256>>>(Wq, Whi + 0 * WSZ, Wlo + 0 * WSZ, WSZ);
    split_kernel<<<(WSZ + 255) / 256, 256>>>(Wk, Whi + 1 * WSZ, Wlo + 1 * WSZ, WSZ);
    split_kernel<<<(WSZ + 255) / 256, 256>>>(Wv, Whi + 2 * WSZ, Wlo + 2 * WSZ, WSZ);
    split_kernel<<<(WSZ + 255) / 256, 256>>>(Wo, Whi + 3 * WSZ, Wlo + 3 * WSZ, WSZ);

    // Q projection -> pack per-head
    hgemm_kernel<128><<<dim3(8, 32, 1), 256>>>(
        Xhi, Xlo, Whi + 0 * WSZ, Wlo + 0 * WSZ, Dmod, Dmod, Dmod, 0, 0, Fb, Dmod, 0);
    qk_pack_kernel<<<OUT_ELEMS / 256, 256>>>(Fb, Qhi, Qlo);
    // K projection
    hgemm_kernel<128><<<dim3(8, 32, 1), 256>>>(
        Xhi, Xlo, Whi + 1 * WSZ, Wlo + 1 * WSZ, Dmod, Dmod, Dmod, 0, 0, Fb, Dmod, 0);
    qk_pack_kernel<<<OUT_ELEMS / 256, 256>>>(Fb, Khi, Klo);
    // V projection -> transposed pack
    hgemm_kernel<128><<<dim3(8, 32, 1), 256>>>(
        Xhi, Xlo, Whi + 2 * WSZ, Wlo + 2 * WSZ, Dmod, Dmod, Dmod, 0, 0, Fb, Dmod, 0);
    v_packT_kernel<<<dim3(Lseq / 32, HD / 32, BH), dim3(32, 8)>>>(Fb, Vthi, Vtlo);

    // S = Q K^T  (batched, K=64)
    hgemm_kernel<128><<<dim3(16, 16, BH), 256>>>(
        Qhi, Qlo, Khi, Klo, HD, HD, HD,
        (long long)Lseq * HD, (long long)Lseq * HD,
        Sb, Lseq, (long long)SEQ2);

    softmax_kernel<<<BH * Lseq, 256>>>(Sb, HL, Phi, Plo);

    // O = P V  (batched, K=2048, N=64) -> [bh][l][64] fp32
    hgemm_kernel<64><<<dim3(1, 16, BH), 256>>>(
        Phi, Plo, Vthi, Vtlo, Lseq, Lseq, Lseq,
        (long long)SEQ2, (long long)HD * Lseq,
        Fb, HD, (long long)Lseq * HD);
    ctx_pack_kernel<<<OUT_ELEMS / 256, 256>>>(Fb, Chi, Clo);

    // out = C Wo^T
    hgemm_kernel<128><<<dim3(8, 32, 1), 256>>>(
        Chi, Clo, Whi + 3 * WSZ, Wlo + 3 * WSZ, Dmod, Dmod, Dmod, 0, 0, outp, Dmod, 0);
}

// round 6
// speedup vs baseline: 2.4938x; 1.3580x over previous
#include <cuda_runtime.h>
#include <cuda_bf16.h>
#include <math.h>
#include <stdint.h>

#define Bsz   2
#define Lseq  2048
#define Dmod  1024
#define Hh    16
#define HD    64
#define MROWS 4096
#define BH    32
#define OUT_ELEMS  (MROWS * Dmod)
#define BIAS_ELEMS (Hh * Lseq * Lseq)

typedef __nv_bfloat16 bf16;

// ---------------- scratch ----------------
__device__ bf16 g_Xhi[MROWS * Dmod], g_Xlo[MROWS * Dmod];
__device__ bf16 g_Whi[4 * Dmod * Dmod], g_Wlo[4 * Dmod * Dmod];
__device__ bf16 g_Qhi[BH * Lseq * HD], g_Qlo[BH * Lseq * HD];
__device__ bf16 g_Khi[BH * Lseq * HD], g_Klo[BH * Lseq * HD];
__device__ bf16 g_Vthi[BH * HD * Lseq], g_Vtlo[BH * HD * Lseq];
__device__ bf16 g_Chi[MROWS * Dmod], g_Clo[MROWS * Dmod];
__device__ float g_F[MROWS * Dmod];                 // fp32 GEMM / flash scratch
__device__ float g_HL[Hh * 4095];
__device__ float g_O[OUT_ELEMS];

// ============================================================
// warp-mma helpers (base PTX sm_80+, assembles at compute_103)
// ============================================================
__device__ __forceinline__ uint32_t smem_u32(const void* p) {
    uint32_t a;
    asm("{ .reg .u64 t; cvta.to.shared.u64 t, %1; cvt.u32.u64 %0, t; }" : "=r"(a) : "l"(p));
    return a;
}
__device__ __forceinline__ void ldsm4(uint32_t* r, uint32_t addr) {
    asm volatile("ldmatrix.sync.aligned.m8n8.x4.shared.b16 {%0,%1,%2,%3}, [%4];"
        : "=r"(r[0]), "=r"(r[1]), "=r"(r[2]), "=r"(r[3]) : "r"(addr));
}
__device__ __forceinline__ void mma_bf16(float* c, const uint32_t* a, const uint32_t* b) {
    asm volatile(
        "mma.sync.aligned.m16n8k16.row.col.f32.bf16.bf16.f32 "
        "{%0,%1,%2,%3}, {%4,%5,%6,%7}, {%8,%9}, {%0,%1,%2,%3};"
        : "+f"(c[0]), "+f"(c[1]), "+f"(c[2]), "+f"(c[3])
        : "r"(a[0]), "r"(a[1]), "r"(a[2]), "r"(a[3]), "r"(b[0]), "r"(b[1]));
}
__device__ __forceinline__ uint32_t packsplit(float x, float y, uint32_t& lo) {
    __nv_bfloat162 h = __floats2bfloat162_rn(x, y);
    float hx = __bfloat162float(h.x), hy = __bfloat162float(h.y);
    __nv_bfloat162 l = __floats2bfloat162_rn(x - hx, y - hy);
    lo = *(uint32_t*)&l;
    return *(uint32_t*)&h;
}

// ============================================================
// T5 bias LUT + bias fill (verified)
// ============================================================
__global__ void build_headlut_kernel(const float* __restrict__ bt, float* __restrict__ hl)
{
    int idx = blockIdx.x * blockDim.x + threadIdx.x;
    if (idx >= Hh * 4095) return;
    int h = idx / 4095;
    int t = idx - h * 4095;
    int rel = t - 2047;
    int bucket = (rel > 0) ? 16 : 0;
    int rp = rel < 0 ? -rel : rel;
    int add;
    if (rp < 8) {
        add = rp;
    } else {
        float v = (logf((float)rp * 0.125f) / 2.772588722239781f) * 8.0f;
        int lv = 8 + (int)v;
        if (rp == 16) lv = 10;
        else if (rp == 32) lv = 12;
        else if (rp == 64) lv = 14;
        add = lv > 15 ? 15 : lv;
    }
    bucket += add;
    hl[idx] = bt[bucket * Hh + h];
}

__global__ void fill_bias_kernel(const float* __restrict__ hl, float* __restrict__ pb)
{
    int i = blockIdx.x;
    int h = blockIdx.y;
    const float* src = hl + h * 4095 + (2047 - i);
    float4* dst = (float4*)(pb + ((size_t)(h * Lseq + i)) * Lseq);
    int j = threadIdx.x * 4;
    dst[threadIdx.x] = make_float4(src[j], src[j + 1], src[j + 2], src[j + 3]);
}

// ============================================================
// elementwise split / pack kernels (verified R5)
// ============================================================
__device__ __forceinline__ void split1(float x, bf16& h, bf16& l) {
    h = __float2bfloat16(x);
    l = __float2bfloat16(x - __bfloat162float(h));
}

__global__ void split_kernel(const float* __restrict__ s, bf16* __restrict__ hi,
                             bf16* __restrict__ lo, int n)
{
    int i = blockIdx.x * 256 + threadIdx.x;
    if (i >= n) return;
    split1(s[i], hi[i], lo[i]);
}

__global__ void qk_pack_kernel(const float* __restrict__ F, bf16* __restrict__ hi,
                               bf16* __restrict__ lo)
{
    int i = blockIdx.x * 256 + threadIdx.x;
    int row = i >> 10, col = i & 1023;
    int b = row >> 11, l = row & 2047, h = col >> 6, d = col & 63;
    size_t o = (((size_t)(b * Hh + h)) * Lseq + l) * HD + d;
    split1(F[i], hi[o], lo[o]);
}

__global__ void v_packT_kernel(const float* __restrict__ F, bf16* __restrict__ hi,
                               bf16* __restrict__ lo)
{
    __shared__ float t[32][33];
    int bh = blockIdx.z, b = bh >> 4, h = bh & 15;
    int l0 = blockIdx.x * 32, d0 = blockIdx.y * 32;
    int tx = threadIdx.x, ty = threadIdx.y;
#pragma unroll
    for (int r = 0; r < 4; ++r) {
        int l = l0 + ty + r * 8;
        t[ty + r * 8][tx] = F[((size_t)(b * Lseq + l)) * Dmod + h * HD + d0 + tx];
    }
    __syncthreads();
#pragma unroll
    for (int r = 0; r < 4; ++r) {
        int d = d0 + ty + r * 8;
        int l = l0 + tx;
        size_t o = ((size_t)bh * HD + d) * Lseq + l;
        split1(t[tx][ty + r * 8], hi[o], lo[o]);
    }
}

__global__ void ctx_pack_kernel(const float* __restrict__ F, bf16* __restrict__ hi,
                                bf16* __restrict__ lo)
{
    int i = blockIdx.x * 256 + threadIdx.x;
    int bh = i >> 17, rest = i & 131071;
    int l = rest >> 6, d = rest & 63;
    int b = bh >> 4, h = bh & 15;
    size_t o = ((size_t)(b * Lseq + l)) * Dmod + h * HD + d;
    split1(F[i], hi[o], lo[o]);
}

// ============================================================
// split-bf16 HMMA GEMM (verified R5): D[M,N] fp32 = A[M,K] * B[N,K]^T
// ============================================================
#define PITCH 40

template<int NTILE>
__global__ void __launch_bounds__(256, 1) hgemm_kernel(
    const bf16* __restrict__ Ahi, const bf16* __restrict__ Alo,
    const bf16* __restrict__ Bhi, const bf16* __restrict__ Blo,
    int lda, int ldb, int kTot,
    long long aBatch, long long bBatch,
    float* __restrict__ outF, long long outLd, long long outBatch)
{
    constexpr int WGN = (NTILE == 128) ? 4 : 2;
    constexpr int WM  = (NTILE == 128) ? 64 : 32;
    constexpr int MF  = WM / 16;
    constexpr int BV  = NTILE * 32 / (256 * 8);

    __shared__ __align__(16) bf16 sAh[128 * PITCH], sAl[128 * PITCH];
    __shared__ __align__(16) bf16 sBh[NTILE * PITCH], sBl[NTILE * PITCH];

    int tid = threadIdx.x, lane = tid & 31, wid = tid >> 5;
    int wm = wid / WGN, wn = wid % WGN;
    int z = blockIdx.z, m0 = blockIdx.y << 7, n0 = blockIdx.x * NTILE;

    const bf16* Abh = Ahi + (size_t)z * aBatch + (size_t)m0 * lda;
    const bf16* Abl = Alo + (size_t)z * aBatch + (size_t)m0 * lda;
    const bf16* Bbh = Bhi + (size_t)z * bBatch + (size_t)n0 * ldb;
    const bf16* Bbl = Blo + (size_t)z * bBatch + (size_t)n0 * ldb;

    uint32_t sAh32 = smem_u32(sAh), sAl32 = smem_u32(sAl);
    uint32_t sBh32 = smem_u32(sBh), sBl32 = smem_u32(sBl);

    float c[MF][4][4];
#pragma unroll
    for (int im = 0; im < MF; ++im)
#pragma unroll
        for (int nf = 0; nf < 4; ++nf)
#pragma unroll
            for (int e = 0; e < 4; ++e) c[im][nf][e] = 0.f;

    uint32_t aOffBase[MF];
#pragma unroll
    for (int im = 0; im < MF; ++im)
        aOffBase[im] = (uint32_t)((wm * WM + im * 16 + (lane & 15)) * PITCH + ((lane >> 4) << 3));
    uint32_t bOffBase[2];
#pragma unroll
    for (int p = 0; p < 2; ++p) {
        int row = wn * 32 + p * 16 + ((lane & 16) >> 1) + (lane & 7);
        int kq = (lane & 8) ? 8 : 0;
        bOffBase[p] = (uint32_t)(row * PITCH + kq);
    }

    int nChunks = kTot >> 5;
    for (int kc = 0; kc < nChunks; ++kc) {
        int k0 = kc << 5;
        uint4 rA[2][2], rB[2][BV];
#pragma unroll
        for (int v = 0; v < 2; ++v) {
            int idx = v * 256 + tid;
            int row = idx >> 2, seg = idx & 3;
            rA[0][v] = *(const uint4*)(Abh + (size_t)row * lda + k0 + seg * 8);
            rA[1][v] = *(const uint4*)(Abl + (size_t)row * lda + k0 + seg * 8);
        }
#pragma unroll
        for (int v = 0; v < BV; ++v) {
            int idx = v * 256 + tid;
            int row = idx >> 2, seg = idx & 3;
            rB[0][v] = *(const uint4*)(Bbh + (size_t)row * ldb + k0 + seg * 8);
            rB[1][v] = *(const uint4*)(Bbl + (size_t)row * ldb + k0 + seg * 8);
        }
        if (kc > 0) __syncthreads();
#pragma unroll
        for (int v = 0; v < 2; ++v) {
            int idx = v * 256 + tid;
            int row = idx >> 2, seg = idx & 3;
            *(uint4*)(sAh + row * PITCH + seg * 8) = rA[0][v];
            *(uint4*)(sAl + row * PITCH + seg * 8) = rA[1][v];
        }
#pragma unroll
        for (int v = 0; v < BV; ++v) {
            int idx = v * 256 + tid;
            int row = idx >> 2, seg = idx & 3;
            *(uint4*)(sBh + row * PITCH + seg * 8) = rB[0][v];
            *(uint4*)(sBl + row * PITCH + seg * 8) = rB[1][v];
        }
        __syncthreads();

#pragma unroll
        for (int ks = 0; ks < 32; ks += 16) {
            uint32_t aH[MF][4], aL[MF][4], bHf[2][4], bLf[2][4];
#pragma unroll
            for (int im = 0; im < MF; ++im) {
                uint32_t off = (aOffBase[im] + ks) * 2;
                ldsm4(aH[im], sAh32 + off);
                ldsm4(aL[im], sAl32 + off);
            }
#pragma unroll
            for (int p = 0; p < 2; ++p) {
                uint32_t off = (bOffBase[p] + ks) * 2;
                ldsm4(bHf[p], sBh32 + off);
                ldsm4(bLf[p], sBl32 + off);
            }
#pragma unroll
            for (int im = 0; im < MF; ++im)
#pragma unroll
                for (int nf = 0; nf < 4; ++nf)
                    mma_bf16(c[im][nf], aH[im], &bHf[nf >> 1][(nf & 1) * 2]);
#pragma unroll
            for (int im = 0; im < MF; ++im)
#pragma unroll
                for (int nf = 0; nf < 4; ++nf)
                    mma_bf16(c[im][nf], aH[im], &bLf[nf >> 1][(nf & 1) * 2]);
#pragma unroll
            for (int im = 0; im < MF; ++im)
#pragma unroll
                for (int nf = 0; nf < 4; ++nf)
                    mma_bf16(c[im][nf], aL[im], &bHf[nf >> 1][(nf & 1) * 2]);
        }
    }

    float* outZ = outF + (size_t)z * outBatch;
#pragma unroll
    for (int im = 0; im < MF; ++im) {
#pragma unroll
        for (int nf = 0; nf < 4; ++nf) {
            int row = m0 + wm * WM + im * 16 + (lane >> 2);
            int col = n0 + wn * 32 + nf * 8 + 2 * (lane & 3);
            float* p0 = outZ + (size_t)row * outLd + col;
            float* p1 = outZ + (size_t)(row + 8) * outLd + col;
            *(float2*)p0 = make_float2(c[im][nf][0], c[im][nf][1]);
            *(float2*)p1 = make_float2(c[im][nf][2], c[im][nf][3]);
        }
    }
}

// ============================================================
// Flash attention (HMMA, split-bf16): per (q-tile 128, bh)
// 8 warps: wm=wid>>1 (4), wn=wid&1 (2). Warp S-tile: 32 x 64.
// ============================================================
#define QP 72
#define VP 136
#define O_QH 0
#define O_QL (O_QH + 128 * QP * 2)
#define O_KH (O_QL + 128 * QP * 2)
#define O_KL (O_KH + 128 * QP * 2)
#define O_VH (O_KL + 128 * QP * 2)
#define O_VL (O_VH + 64 * VP * 2)
#define O_WIN (O_VL + 64 * VP * 2)
#define O_PM  (O_WIN + 256 * 4)
#define O_PS  (O_PM + 256 * 4)
#define O_M   (O_PS + 256 * 4)
#define O_L   (O_M + 128 * 4)
#define O_AL  (O_L + 128 * 4)
#define O_OB  (O_AL + 128 * 4)
#define FLASH_SMEM (O_OB + 128 * 64 * 4)

__global__ void __launch_bounds__(256, 1) flash_kernel(
    const bf16* __restrict__ Qhi, const bf16* __restrict__ Qlo,
    const bf16* __restrict__ Khi, const bf16* __restrict__ Klo,
    const bf16* __restrict__ Vthi, const bf16* __restrict__ Vtlo,
    const float* __restrict__ hl, float* __restrict__ Fout)
{
    extern __shared__ char smc[];
    bf16* sQh = (bf16*)(smc + O_QH);
    bf16* sQl = (bf16*)(smc + O_QL);
    bf16* sKh = (bf16*)(smc + O_KH);
    bf16* sKl = (bf16*)(smc + O_KL);
    bf16* sVh = (bf16*)(smc + O_VH);
    bf16* sVl = (bf16*)(smc + O_VL);
    float* win = (float*)(smc + O_WIN);
    float* pm  = (float*)(smc + O_PM);
    float* ps  = (float*)(smc + O_PS);
    float* smM = (float*)(smc + O_M);
    float* smL = (float*)(smc + O_L);
    float* smA = (float*)(smc + O_AL);
    float* obuf = (float*)(smc + O_OB);

    int tid = threadIdx.x, lane = tid & 31, wid = tid >> 5;
    int wm = wid >> 1, wn = wid & 1;
    int q0 = blockIdx.x << 7;
    int bh = blockIdx.y;
    int h = bh & 15;
    const bf16* Qbh = Qhi + (size_t)bh * Lseq * HD;
    const bf16* Qbl = Qlo + (size_t)bh * Lseq * HD;
    const bf16* Kbh = Khi + (size_t)bh * Lseq * HD;
    const bf16* Kbl = Klo + (size_t)bh * Lseq * HD;
    const bf16* Vbh = Vthi + (size_t)bh * HD * Lseq;
    const bf16* Vbl = Vtlo + (size_t)bh * HD * Lseq;
    const float* hlh = hl + h * 4095;

    // Q tile -> smem
#pragma unroll
    for (int v = 0; v < 4; ++v) {
        int idx = v * 256 + tid;
        int row = idx >> 3, seg = idx & 7;
        *(uint4*)(sQh + row * QP + seg * 8) = *(const uint4*)(Qbh + (size_t)(q0 + row) * HD + seg * 8);
        *(uint4*)(sQl + row * QP + seg * 8) = *(const uint4*)(Qbl + (size_t)(q0 + row) * HD + seg * 8);
    }
    if (tid < 128) { smM[tid] = -1e30f; smL[tid] = 0.f; }

    uint32_t sQh32 = smem_u32(sQh), sQl32 = smem_u32(sQl);
    uint32_t sKh32 = smem_u32(sKh), sKl32 = smem_u32(sKl);
    uint32_t sVh32 = smem_u32(sVh), sVl32 = smem_u32(sVl);

    uint32_t qOff[2];
#pragma unroll
    for (int im = 0; im < 2; ++im)
        qOff[im] = (uint32_t)(((wm * 32 + im * 16 + (lane & 15)) * QP + ((lane >> 4) << 3)) * 2);
    uint32_t kOff[4], vOff[4];
#pragma unroll
    for (int p = 0; p < 4; ++p) {
        int kq = (lane & 8) ? 8 : 0;
        kOff[p] = (uint32_t)(((wn * 64 + p * 16 + ((lane & 16) >> 1) + (lane & 7)) * QP + kq) * 2);
        vOff[p] = (uint32_t)(((p * 16 + ((lane & 16) >> 1) + (lane & 7)) * VP + wn * 64 + kq) * 2);
    }

    int rbase = wm * 32 + (lane >> 2);          // warp's row for im=0
    int cbase = wn * 64 + 2 * (lane & 3);       // warp's col base

    float O[2][8][4];
#pragma unroll
    for (int im = 0; im < 2; ++im)
#pragma unroll
        for (int nf = 0; nf < 8; ++nf)
#pragma unroll
            for (int e = 0; e < 4; ++e) O[im][nf][e] = 0.f;

    for (int kt = 0; kt < Lseq / 128; ++kt) {
        int k0 = kt << 7;
        // global -> regs
        uint4 rKh[4], rKl[4], rVh[4], rVl[4];
#pragma unroll
        for (int v = 0; v < 4; ++v) {
            int idx = v * 256 + tid;
            int row = idx >> 3, seg = idx & 7;
            rKh[v] = *(const uint4*)(Kbh + (size_t)(k0 + row) * HD + seg * 8);
            rKl[v] = *(const uint4*)(Kbl + (size_t)(k0 + row) * HD + seg * 8);
            int vrow = idx >> 4, vseg = idx & 15;
            rVh[v] = *(const uint4*)(Vbh + (size_t)vrow * Lseq + k0 + vseg * 8);
            rVl[v] = *(const uint4*)(Vbl + (size_t)vrow * Lseq + k0 + vseg * 8);
        }
        float winv = 0.f;
        if (tid < 255) winv = hlh[k0 - q0 + 1920 + tid];

        __syncthreads();   // prev iteration smem reads done
#pragma unroll
        for (int v = 0; v < 4; ++v) {
            int idx = v * 256 + tid;
            int row = idx >> 3, seg = idx & 7;
            *(uint4*)(sKh + row * QP + seg * 8) = rKh[v];
            *(uint4*)(sKl + row * QP + seg * 8) = rKl[v];
            int vrow = idx >> 4, vseg = idx & 15;
            *(uint4*)(sVh + vrow * VP + vseg * 8) = rVh[v];
            *(uint4*)(sVl + vrow * VP + vseg * 8) = rVl[v];
        }
        if (tid < 255) win[tid] = winv;
        __syncthreads();

        // ---- S = Q K^T (3-term split) ----
        float c[2][8][4];
#pragma unroll
        for (int im = 0; im < 2; ++im)
#pragma unroll
            for (int nf = 0; nf < 8; ++nf)
#pragma unroll
                for (int e = 0; e < 4; ++e) c[im][nf][e] = 0.f;
#pragma unroll
        for (int ks = 0; ks < 64; ks += 16) {
            uint32_t aH[2][4], aL[2][4], bH[4][4], bL[4][4];
#pragma unroll
            for (int im = 0; im < 2; ++im) {
                ldsm4(aH[im], sQh32 + qOff[im] + ks * 2);
                ldsm4(aL[im], sQl32 + qOff[im] + ks * 2);
            }
#pragma unroll
            for (int p = 0; p < 4; ++p) {
                ldsm4(bH[p], sKh32 + kOff[p] + ks * 2);
                ldsm4(bL[p], sKl32 + kOff[p] + ks * 2);
            }
#pragma unroll
            for (int im = 0; im < 2; ++im)
#pragma unroll
                for (int nf = 0; nf < 8; ++nf)
                    mma_bf16(c[im][nf], aH[im], &bH[nf >> 1][(nf & 1) * 2]);
#pragma unroll
            for (int im = 0; im < 2; ++im)
#pragma unroll
                for (int nf = 0; nf < 8; ++nf)
                    mma_bf16(c[im][nf], aH[im], &bL[nf >> 1][(nf & 1) * 2]);
#pragma unroll
            for (int im = 0; im < 2; ++im)
#pragma unroll
                for (int nf = 0; nf < 8; ++nf)
                    mma_bf16(c[im][nf], aL[im], &bH[nf >> 1][(nf & 1) * 2]);
        }

        // ---- bias + partial row max ----
#pragma unroll
        for (int im = 0; im < 2; ++im) {
            int row = rbase + im * 16;
            float ma = -1e30f, mb = -1e30f;
#pragma unroll
            for (int nf = 0; nf < 8; ++nf) {
                int idx = cbase + nf * 8 - row + 127;
                c[im][nf][0] += win[idx];
                c[im][nf][1] += win[idx + 1];
                c[im][nf][2] += win[idx - 8];
                c[im][nf][3] += win[idx - 7];
                ma = fmaxf(ma, fmaxf(c[im][nf][0], c[im][nf][1]));
                mb = fmaxf(mb, fmaxf(c[im][nf][2], c[im][nf][3]));
            }
            ma = fmaxf(ma, __shfl_xor_sync(0xffffffffu, ma, 1));
            ma = fmaxf(ma, __shfl_xor_sync(0xffffffffu, ma, 2));
            mb = fmaxf(mb, __shfl_xor_sync(0xffffffffu, mb, 1));
            mb = fmaxf(mb, __shfl_xor_sync(0xffffffffu, mb, 2));
            if ((lane & 3) == 0) {
                pm[row * 2 + wn] = ma;
                pm[(row + 8) * 2 + wn] = mb;
            }
        }
        __syncthreads();
        if (tid < 128) {
            float mo = smM[tid];
            float mn = fmaxf(mo, fmaxf(pm[tid * 2], pm[tid * 2 + 1]));
            smA[tid] = expf(mo - mn);
            smM[tid] = mn;
        }
        __syncthreads();

        // ---- exp, partial sums, O rescale ----
#pragma unroll
        for (int im = 0; im < 2; ++im) {
            int row = rbase + im * 16;
            float mr = smM[row], mr8 = smM[row + 8];
            float sa = 0.f, sb = 0.f;
#pragma unroll
            for (int nf = 0; nf < 8; ++nf) {
                c[im][nf][0] = expf(c[im][nf][0] - mr);
                c[im][nf][1] = expf(c[im][nf][1] - mr);
                c[im][nf][2] = expf(c[im][nf][2] - mr8);
                c[im][nf][3] = expf(c[im][nf][3] - mr8);
                sa += c[im][nf][0] + c[im][nf][1];
                sb += c[im][nf][2] + c[im][nf][3];
            }
            sa += __shfl_xor_sync(0xffffffffu, sa, 1);
            sa += __shfl_xor_sync(0xffffffffu, sa, 2);
            sb += __shfl_xor_sync(0xffffffffu, sb, 1);
            sb += __shfl_xor_sync(0xffffffffu, sb, 2);
            if ((lane & 3) == 0) {
                ps[row * 2 + wn] = sa;
                ps[(row + 8) * 2 + wn] = sb;
            }
            float al = smA[row], al8 = smA[row + 8];
#pragma unroll
            for (int nf = 0; nf < 8; ++nf) {
                O[im][nf][0] *= al;  O[im][nf][1] *= al;
                O[im][nf][2] *= al8; O[im][nf][3] *= al8;
            }
        }
        __syncthreads();
        if (tid < 128)
            smL[tid] = smL[tid] * smA[tid] + ps[tid * 2] + ps[tid * 2 + 1];

        // ---- O += P V (3-term split; P fragments straight from registers) ----
#pragma unroll
        for (int kp = 0; kp < 4; ++kp) {
            uint32_t aPh[2][4], aPl[2][4];
#pragma unroll
            for (int im = 0; im < 2; ++im) {
                aPh[im][0] = packsplit(c[im][2 * kp][0],     c[im][2 * kp][1],     aPl[im][0]);
                aPh[im][1] = packsplit(c[im][2 * kp][2],     c[im][2 * kp][3],     aPl[im][1]);
                aPh[im][2] = packsplit(c[im][2 * kp + 1][0], c[im][2 * kp + 1][1], aPl[im][2]);
                aPh[im][3] = packsplit(c[im][2 * kp + 1][2], c[im][2 * kp + 1][3], aPl[im][3]);
            }
            uint32_t vH[4][4], vL[4][4];
#pragma unroll
            for (int p = 0; p < 4; ++p) {
                ldsm4(vH[p], sVh32 + vOff[p] + kp * 32);
                ldsm4(vL[p], sVl32 + vOff[p] + kp * 32);
            }
#pragma unroll
            for (int im = 0; im < 2; ++im)
#pragma unroll
                for (int nf = 0; nf < 8; ++nf)
                    mma_bf16(O[im][nf], aPh[im], &vH[nf >> 1][(nf & 1) * 2]);
#pragma unroll
            for (int im = 0; im < 2; ++im)
#pragma unroll
                for (int nf = 0; nf < 8; ++nf)
                    mma_bf16(O[im][nf], aPl[im], &vH[nf >> 1][(nf & 1) * 2]);
#pragma unroll
            for (int im = 0; im < 2; ++im)
#pragma unroll
                for (int nf = 0; nf < 8; ++nf)
                    mma_bf16(O[im][nf], aPh[im], &vL[nf >> 1][(nf & 1) * 2]);
        }
    }

    // ---- cross-warp O reduction + normalize + write ----
    if (wn == 1) {
#pragma unroll
        for (int im = 0; im < 2; ++im) {
            int row = rbase + im * 16;
#pragma unroll
            for (int nf = 0; nf < 8; ++nf) {
                int col = nf * 8 + 2 * (lane & 3);
                *(float2*)(obuf + row * 64 + col)       = make_float2(O[im][nf][0], O[im][nf][1]);
                *(float2*)(obuf + (row + 8) * 64 + col) = make_float2(O[im][nf][2], O[im][nf][3]);
            }
        }
    }
    __syncthreads();
    if (wn == 0) {
#pragma unroll
        for (int im = 0; im < 2; ++im) {
            int row = rbase + im * 16;
            float inv = 1.f / smL[row], inv8 = 1.f / smL[row + 8];
#pragma unroll
            for (int nf = 0; nf < 8; ++nf) {
                int col = nf * 8 + 2 * (lane & 3);
                float2 o0 = *(float2*)(obuf + row * 64 + col);
                float2 o1 = *(float2*)(obuf + (row + 8) * 64 + col);
                float* p0 = Fout + ((size_t)bh * Lseq + q0 + row) * HD + col;
                float* p1 = Fout + ((size_t)bh * Lseq + q0 + row + 8) * HD + col;
                *(float2*)p0 = make_float2((O[im][nf][0] + o0.x) * inv,  (O[im][nf][1] + o0.y) * inv);
                *(float2*)p1 = make_float2((O[im][nf][2] + o1.x) * inv8, (O[im][nf][3] + o1.y) * inv8);
            }
        }
    }
}

// ============================================================
extern "C" void kernel_launch(void* const* d_in, const int* in_sizes, int n_in,
                              void* d_out, int out_size)
{
    const float* X  = (const float*)d_in[0];
    const float* Wq = (const float*)d_in[1];
    const float* Wk = (const float*)d_in[2];
    const float* Wv = (const float*)d_in[3];
    const float* Wo = (const float*)d_in[4];
    const float* bt = (const float*)d_in[5];
    float* out = (float*)d_out;

    void *pXhi, *pXlo, *pWhi, *pWlo, *pQhi, *pQlo, *pKhi, *pKlo,
         *pVthi, *pVtlo, *pChi, *pClo, *pF, *pHL, *pO;
    cudaGetSymbolAddress(&pXhi, g_Xhi);   cudaGetSymbolAddress(&pXlo, g_Xlo);
    cudaGetSymbolAddress(&pWhi, g_Whi);   cudaGetSymbolAddress(&pWlo, g_Wlo);
    cudaGetSymbolAddress(&pQhi, g_Qhi);   cudaGetSymbolAddress(&pQlo, g_Qlo);
    cudaGetSymbolAddress(&pKhi, g_Khi);   cudaGetSymbolAddress(&pKlo, g_Klo);
    cudaGetSymbolAddress(&pVthi, g_Vthi); cudaGetSymbolAddress(&pVtlo, g_Vtlo);
    cudaGetSymbolAddress(&pChi, g_Chi);   cudaGetSymbolAddress(&pClo, g_Clo);
    cudaGetSymbolAddress(&pF, g_F);
    cudaGetSymbolAddress(&pHL, g_HL);     cudaGetSymbolAddress(&pO, g_O);

    bf16 *Xhi = (bf16*)pXhi, *Xlo = (bf16*)pXlo;
    bf16 *Whi = (bf16*)pWhi, *Wlo = (bf16*)pWlo;
    bf16 *Qhi = (bf16*)pQhi, *Qlo = (bf16*)pQlo;
    bf16 *Khi = (bf16*)pKhi, *Klo = (bf16*)pKlo;
    bf16 *Vthi = (bf16*)pVthi, *Vtlo = (bf16*)pVtlo;
    bf16 *Chi = (bf16*)pChi, *Clo = (bf16*)pClo;
    float *Fb = (float*)pF, *HL = (float*)pHL, *Ob = (float*)pO;

    float* outp = Ob;
    float* pbp  = nullptr;
    long long osz = (long long)out_size;
    if (osz >= (long long)OUT_ELEMS + (long long)BIAS_ELEMS) {
        outp = out; pbp = out + (osz - (long long)BIAS_ELEMS);
    } else if (osz == (long long)BIAS_ELEMS) {
        pbp = out;
    } else if (osz >= (long long)OUT_ELEMS) {
        outp = out;
    }

    const int WSZ = Dmod * Dmod;

    cudaFuncSetAttribute(flash_kernel, cudaFuncAttributeMaxDynamicSharedMemorySize, FLASH_SMEM);

    build_headlut_kernel<<<(Hh * 4095 + 255) / 256, 256>>>(bt, HL);
    if (pbp) fill_bias_kernel<<<dim3(Lseq, Hh), 512>>>(HL, pbp);

    split_kernel<<<(OUT_ELEMS + 255) / 256, 256>>>(X, Xhi, Xlo, OUT_ELEMS);
    split_kernel<<<(WSZ + 255) / 256, 256>>>(Wq, Whi + 0 * WSZ, Wlo + 0 * WSZ, WSZ);
    split_kernel<<<(WSZ + 255) / 256, 256>>>(Wk, Whi + 1 * WSZ, Wlo + 1 * WSZ, WSZ);
    split_kernel<<<(WSZ + 255) / 256, 256>>>(Wv, Whi + 2 * WSZ, Wlo + 2 * WSZ, WSZ);
    split_kernel<<<(WSZ + 255) / 256, 256>>>(Wo, Whi + 3 * WSZ, Wlo + 3 * WSZ, WSZ);

    hgemm_kernel<128><<<dim3(8, 32, 1), 256>>>(
        Xhi, Xlo, Whi + 0 * WSZ, Wlo + 0 * WSZ, Dmod, Dmod, Dmod, 0, 0, Fb, Dmod, 0);
    qk_pack_kernel<<<OUT_ELEMS / 256, 256>>>(Fb, Qhi, Qlo);
    hgemm_kernel<128><<<dim3(8, 32, 1), 256>>>(
        Xhi, Xlo, Whi + 1 * WSZ, Wlo + 1 * WSZ, Dmod, Dmod, Dmod, 0, 0, Fb, Dmod, 0);
    qk_pack_kernel<<<OUT_ELEMS / 256, 256>>>(Fb, Khi, Klo);
    hgemm_kernel<128><<<dim3(8, 32, 1), 256>>>(
        Xhi, Xlo, Whi + 2 * WSZ, Wlo + 2 * WSZ, Dmod, Dmod, Dmod, 0, 0, Fb, Dmod, 0);
    v_packT_kernel<<<dim3(Lseq / 32, HD / 32, BH), dim3(32, 8)>>>(Fb, Vthi, Vtlo);

    // fused attention -> Fb [bh][l][64]
    flash_kernel<<<dim3(Lseq / 128, BH), 256, FLASH_SMEM>>>(
        Qhi, Qlo, Khi, Klo, Vthi, Vtlo, HL, Fb);
    ctx_pack_kernel<<<OUT_ELEMS / 256, 256>>>(Fb, Chi, Clo);

    hgemm_kernel<128><<<dim3(8, 32, 1), 256>>>(
        Chi, Clo, Whi + 3 * WSZ, Wlo + 3 * WSZ, Dmod, Dmod, Dmod, 0, 0, outp, Dmod, 0);
}